// round 1
// baseline (speedup 1.0000x reference)
#include <cuda_runtime.h>

// Problem dims (fixed by the reference: T=2048, B=32, D=512)
#define T_DIM 2048
#define B_DIM 32
#define D_DIM 512
#define M_DIM (T_DIM * B_DIM)   // 65536 rows of the GEMM
#define BD    (B_DIM * D_DIM)   // 16384 independent scan lanes

// Scratch: Y = x @ W^T + b  (fp32, 134 MB) and packed backward-scan spikes (4 MB).
__device__ float        g_Y[(size_t)M_DIM * D_DIM];
__device__ unsigned int g_bits[((size_t)M_DIM * D_DIM) / 32];

// ---------------------------------------------------------------------------
// SGEMM: Y[m, e] = sum_k X[m, k] * W[e, k] + bias[e]
// X is [M, 512] row-major (x viewed as [T*B, D]); W is [512, 512] row-major.
// Classic 128x128x8 SIMT tile, 256 threads, 8x8 per-thread accumulators.
// Sequential-k fp32 FMA accumulation (accuracy-first for the spike threshold).
// ---------------------------------------------------------------------------
#define BM 128
#define BN 128
#define BK 8
#define TM 8
#define TN 8

__global__ __launch_bounds__(256, 2)
void sgemm_kernel(const float* __restrict__ X, const float* __restrict__ W,
                  const float* __restrict__ bias) {
    __shared__ __align__(16) float As[BK][BM];
    __shared__ __align__(16) float Bs[BK][BN];

    const int bm  = blockIdx.y * BM;
    const int bn  = blockIdx.x * BN;
    const int tid = threadIdx.x;
    const int tx  = tid & 15;    // n-direction thread coord (0..15)
    const int ty  = tid >> 4;    // m-direction thread coord (0..15)

    // global->smem load mapping: one float4 per thread per operand per k-tile
    const int lr = tid >> 1;          // row within 128-row tile
    const int lc = (tid & 1) << 2;    // col 0 or 4 within 8-wide k-tile

    float acc[TM][TN];
#pragma unroll
    for (int i = 0; i < TM; i++)
#pragma unroll
        for (int j = 0; j < TN; j++) acc[i][j] = 0.0f;

    const float* Xrow = X + (size_t)(bm + lr) * D_DIM + lc;
    const float* Wrow = W + (size_t)(bn + lr) * D_DIM + lc;

    for (int k0 = 0; k0 < D_DIM; k0 += BK) {
        float4 a4 = *(const float4*)(Xrow + k0);
        float4 b4 = *(const float4*)(Wrow + k0);
        As[lc + 0][lr] = a4.x; As[lc + 1][lr] = a4.y;
        As[lc + 2][lr] = a4.z; As[lc + 3][lr] = a4.w;
        Bs[lc + 0][lr] = b4.x; Bs[lc + 1][lr] = b4.y;
        Bs[lc + 2][lr] = b4.z; Bs[lc + 3][lr] = b4.w;
        __syncthreads();

#pragma unroll
        for (int k = 0; k < BK; k++) {
            float4 a0 = *(const float4*)&As[k][ty * TM];
            float4 a1 = *(const float4*)&As[k][ty * TM + 4];
            float4 b0 = *(const float4*)&Bs[k][tx * TN];
            float4 b1 = *(const float4*)&Bs[k][tx * TN + 4];
            float ar[TM] = {a0.x, a0.y, a0.z, a0.w, a1.x, a1.y, a1.z, a1.w};
            float br[TN] = {b0.x, b0.y, b0.z, b0.w, b1.x, b1.y, b1.z, b1.w};
#pragma unroll
            for (int i = 0; i < TM; i++)
#pragma unroll
                for (int j = 0; j < TN; j++)
                    acc[i][j] = fmaf(ar[i], br[j], acc[i][j]);
        }
        __syncthreads();
    }

    // Epilogue: add bias, store Y
#pragma unroll
    for (int i = 0; i < TM; i++) {
        const size_t row = (size_t)(bm + ty * TM + i);
#pragma unroll
        for (int j = 0; j < TN; j += 4) {
            const int e = bn + tx * TN + j;
            float4 o;
            o.x = acc[i][j + 0] + bias[e + 0];
            o.y = acc[i][j + 1] + bias[e + 1];
            o.z = acc[i][j + 2] + bias[e + 2];
            o.w = acc[i][j + 3] + bias[e + 3];
            *(float4*)(g_Y + row * D_DIM + e) = o;
        }
    }
}

// ---------------------------------------------------------------------------
// LIF step (exact fp32 match of the reference):
//   v = v + (c - v) * 0.5 ;  s = (v >= 1) ;  v = s ? 0 : v
// Backward scan (t = T-1 .. 0) packs spikes into g_bits via warp ballot.
// ---------------------------------------------------------------------------
#define UNR 32

__global__ void scan_bwd_kernel() {
    const int l = blockIdx.x * blockDim.x + threadIdx.x;   // lane in [0, BD)
    float v = 0.0f;
    for (int t0 = T_DIM - 1; t0 >= 0; t0 -= UNR) {
        float c[UNR];
#pragma unroll
        for (int i = 0; i < UNR; i++)
            c[i] = g_Y[(size_t)(t0 - i) * BD + l];
#pragma unroll
        for (int i = 0; i < UNR; i++) {
            v = v + (c[i] - v) * 0.5f;
            const bool s = (v >= 1.0f);
            const unsigned m = __ballot_sync(0xffffffffu, s);
            if ((threadIdx.x & 31) == 0)
                g_bits[((size_t)(t0 - i) * BD + l) >> 5] = m;
            v = s ? 0.0f : v;
        }
    }
}

// Forward scan (t = 0 .. T-1), fused with final add:
//   out[t] = s_fwd[t] + s_bwd_bit[t]
__global__ void scan_fwd_kernel(float* __restrict__ out) {
    const int l    = blockIdx.x * blockDim.x + threadIdx.x;
    const int lane = threadIdx.x & 31;
    float v = 0.0f;
    for (int t0 = 0; t0 < T_DIM; t0 += UNR) {
        float c[UNR];
        unsigned w[UNR];
#pragma unroll
        for (int i = 0; i < UNR; i++)
            c[i] = g_Y[(size_t)(t0 + i) * BD + l];
#pragma unroll
        for (int i = 0; i < UNR; i++)
            w[i] = g_bits[((size_t)(t0 + i) * BD + l) >> 5];
#pragma unroll
        for (int i = 0; i < UNR; i++) {
            v = v + (c[i] - v) * 0.5f;
            const bool s = (v >= 1.0f);
            const float o = (s ? 1.0f : 0.0f) + (float)((w[i] >> lane) & 1u);
            out[(size_t)(t0 + i) * BD + l] = o;
            v = s ? 0.0f : v;
        }
    }
}

// ---------------------------------------------------------------------------
// Launch: GEMM -> backward scan (bit-pack) -> forward scan (+add, write out)
// ---------------------------------------------------------------------------
extern "C" void kernel_launch(void* const* d_in, const int* in_sizes, int n_in,
                              void* d_out, int out_size) {
    const float* x = (const float*)d_in[0];   // [T, B, D]
    const float* W = (const float*)d_in[1];   // [D, D]
    const float* b = (const float*)d_in[2];   // [D]
    float* out = (float*)d_out;               // [T, B, D]

    dim3 grid(D_DIM / BN, M_DIM / BM);        // (4, 512)
    sgemm_kernel<<<grid, 256>>>(x, W, b);
    scan_bwd_kernel<<<BD / 256, 256>>>();
    scan_fwd_kernel<<<BD / 256, 256>>>(out);
}

// round 2
// speedup vs baseline: 1.4579x; 1.4579x over previous
#include <cuda_runtime.h>

// Problem dims (fixed: T=2048, B=32, D=512)
#define T_DIM 2048
#define B_DIM 32
#define D_DIM 512
#define M_DIM (T_DIM * B_DIM)   // 65536 GEMM rows
#define BD    (B_DIM * D_DIM)   // 16384 scan lanes

// Scratch: Y = x @ W^T + b (fp32, 134 MB)
__device__ float g_Y[(size_t)M_DIM * D_DIM];

// ---------------------------------------------------------------------------
// SGEMM: Y[m,e] = sum_k X[m,k] * W[e,k] + bias[e]
// 128x128x16 tile, 256 threads, double-buffered smem,
// warp tile 32m x 64n, thread tile 4m x 16n (conflict-free/broadcast LDS).
// k ascending -> bit-identical to round-1 Y.
// ---------------------------------------------------------------------------
#define BM 128
#define BN 128
#define BK 16
#define NKT (D_DIM / BK)   // 32 k-tiles

__global__ __launch_bounds__(256, 2)
void sgemm_kernel(const float* __restrict__ X, const float* __restrict__ Wm,
                  const float* __restrict__ bias) {
    __shared__ __align__(16) float As[2][BK][BM];
    __shared__ __align__(16) float Bs[2][BK][BN];

    const int tid  = threadIdx.x;
    const int bm   = blockIdx.y * BM;
    const int bn   = blockIdx.x * BN;

    // compute-thread mapping: 8 warps as 4(m) x 2(n); warp tile 32m x 64n
    const int wid    = tid >> 5;
    const int lane   = tid & 31;
    const int warp_m = wid >> 1;          // 0..3
    const int warp_n = wid & 1;           // 0..1
    const int lm     = lane >> 2;         // 0..7
    const int ln     = lane & 3;          // 0..3
    const int tm0    = warp_m * 32 + lm * 4;   // 4 consecutive m rows
    const int tn0    = warp_n * 64 + ln * 4;   // + j4*16, j4=0..3

    // global-load mapping: 4 threads per row (64B contiguous), 2 row-passes
    const int gr = tid >> 2;              // 0..63
    const int gk = (tid & 3) << 2;        // 0,4,8,12

    const float* Xg = X  + (size_t)(bm + gr) * D_DIM + gk;
    const float* Wg = Wm + (size_t)(bn + gr) * D_DIM + gk;

    float acc[4][16];
#pragma unroll
    for (int i = 0; i < 4; i++)
#pragma unroll
        for (int j = 0; j < 16; j++) acc[i][j] = 0.0f;

    // prologue: tile 0 -> smem[0]
    {
        float4 a0 = *(const float4*)(Xg);
        float4 a1 = *(const float4*)(Xg + (size_t)64 * D_DIM);
        float4 b0 = *(const float4*)(Wg);
        float4 b1 = *(const float4*)(Wg + (size_t)64 * D_DIM);
#pragma unroll
        for (int c = 0; c < 4; c++) {
            As[0][gk + c][gr]      = ((const float*)&a0)[c];
            As[0][gk + c][gr + 64] = ((const float*)&a1)[c];
            Bs[0][gk + c][gr]      = ((const float*)&b0)[c];
            Bs[0][gk + c][gr + 64] = ((const float*)&b1)[c];
        }
    }
    __syncthreads();

    int buf = 0;
    for (int kt = 1; kt <= NKT; kt++) {
        float4 na0, na1, nb0, nb1;
        if (kt < NKT) {
            const int k0 = kt * BK;
            na0 = *(const float4*)(Xg + k0);
            na1 = *(const float4*)(Xg + k0 + (size_t)64 * D_DIM);
            nb0 = *(const float4*)(Wg + k0);
            nb1 = *(const float4*)(Wg + k0 + (size_t)64 * D_DIM);
        }

#pragma unroll
        for (int k = 0; k < BK; k++) {
            float4 af = *(const float4*)&As[buf][k][tm0];
            float  a[4] = {af.x, af.y, af.z, af.w};
            float  b[16];
#pragma unroll
            for (int j4 = 0; j4 < 4; j4++) {
                float4 bf = *(const float4*)&Bs[buf][k][tn0 + j4 * 16];
                b[j4 * 4 + 0] = bf.x; b[j4 * 4 + 1] = bf.y;
                b[j4 * 4 + 2] = bf.z; b[j4 * 4 + 3] = bf.w;
            }
#pragma unroll
            for (int i = 0; i < 4; i++)
#pragma unroll
                for (int j = 0; j < 16; j++)
                    acc[i][j] = fmaf(a[i], b[j], acc[i][j]);
        }

        if (kt < NKT) {
            const int nb = buf ^ 1;
#pragma unroll
            for (int c = 0; c < 4; c++) {
                As[nb][gk + c][gr]      = ((const float*)&na0)[c];
                As[nb][gk + c][gr + 64] = ((const float*)&na1)[c];
                Bs[nb][gk + c][gr]      = ((const float*)&nb0)[c];
                Bs[nb][gk + c][gr + 64] = ((const float*)&nb1)[c];
            }
        }
        __syncthreads();
        buf ^= 1;
    }

    // epilogue: + bias, store Y
#pragma unroll
    for (int j4 = 0; j4 < 4; j4++) {
        const int e = bn + tn0 + j4 * 16;
        float4 bi = *(const float4*)(bias + e);
#pragma unroll
        for (int i = 0; i < 4; i++) {
            float4 o;
            o.x = acc[i][j4 * 4 + 0] + bi.x;
            o.y = acc[i][j4 * 4 + 1] + bi.y;
            o.z = acc[i][j4 * 4 + 2] + bi.z;
            o.w = acc[i][j4 * 4 + 3] + bi.w;
            *(float4*)(g_Y + (size_t)(bm + tm0 + i) * D_DIM + e) = o;
        }
    }
}

// ---------------------------------------------------------------------------
// Fused fwd+bwd LIF scan, time-chunked with warm-up.
// v' = v + (c - v)*0.5 contracts exactly (x0.5 is exact); spikes hard-reset
// to 0. W_UP=96 warm-up steps from v=0 reproduce true state to < 2^-96
// (or exactly on any warm-up spike). out[t] = s_fwd[t] + s_bwd[t].
// ---------------------------------------------------------------------------
#define L_CH  256
#define W_UP  96
#define NCH   (T_DIM / L_CH)   // 8 chunks
#define UNR   16

__device__ __forceinline__ void lif_step(float& v, float c, bool& s) {
    v = v + (c - v) * 0.5f;
    s = (v >= 1.0f);
    v = s ? 0.0f : v;
}

__global__ void scan_kernel(float* __restrict__ out) {
    const int l  = blockIdx.x * blockDim.x + threadIdx.x;   // lane in [0, BD)
    const int t0 = blockIdx.y * L_CH;

    unsigned fb[L_CH / 32];   // fwd spike bits for this chunk

    // ---- forward pass ----
    float v = 0.0f;
    {
        const int tb = (t0 - W_UP < 0) ? 0 : (t0 - W_UP);   // warm-up start
        for (int tw = tb; tw < t0; tw += UNR) {             // W_UP multiple of UNR
            float c[UNR];
#pragma unroll
            for (int i = 0; i < UNR; i++) c[i] = g_Y[(size_t)(tw + i) * BD + l];
#pragma unroll
            for (int i = 0; i < UNR; i++) { bool s; lif_step(v, c[i], s); }
        }
#pragma unroll
        for (int w = 0; w < L_CH / 32; w++) {
            unsigned bits = 0;
#pragma unroll 1
            for (int h = 0; h < 2; h++) {
                float c[UNR];
#pragma unroll
                for (int i = 0; i < UNR; i++)
                    c[i] = g_Y[(size_t)(t0 + w * 32 + h * UNR + i) * BD + l];
#pragma unroll
                for (int i = 0; i < UNR; i++) {
                    bool s; lif_step(v, c[i], s);
                    bits |= (unsigned)s << (h * UNR + i);
                }
            }
            fb[w] = bits;
        }
    }

    // ---- backward pass (+ fused add & store) ----
    v = 0.0f;
    {
        const int te = (t0 + L_CH + W_UP > T_DIM) ? T_DIM : (t0 + L_CH + W_UP);
        for (int tw = te; tw > t0 + L_CH; tw -= UNR) {
            float c[UNR];
#pragma unroll
            for (int i = 0; i < UNR; i++) c[i] = g_Y[(size_t)(tw - 1 - i) * BD + l];
#pragma unroll
            for (int i = 0; i < UNR; i++) { bool s; lif_step(v, c[i], s); }
        }
#pragma unroll
        for (int w = L_CH / 32 - 1; w >= 0; w--) {
            const unsigned bits = fb[w];
#pragma unroll 1
            for (int h = 1; h >= 0; h--) {
                float c[UNR];
#pragma unroll
                for (int i = 0; i < UNR; i++)
                    c[i] = g_Y[(size_t)(t0 + w * 32 + h * UNR + (UNR - 1) - i) * BD + l];
#pragma unroll
                for (int i = 0; i < UNR; i++) {
                    const int ti = h * UNR + (UNR - 1) - i;   // within-chunk t
                    bool s; lif_step(v, c[i], s);
                    out[(size_t)(t0 + w * 32 + ti) * BD + l] =
                        (s ? 1.0f : 0.0f) + (float)((bits >> ti) & 1u);
                }
            }
        }
    }
}

// ---------------------------------------------------------------------------
extern "C" void kernel_launch(void* const* d_in, const int* in_sizes, int n_in,
                              void* d_out, int out_size) {
    const float* x = (const float*)d_in[0];   // [T, B, D]
    const float* W = (const float*)d_in[1];   // [D, D]
    const float* b = (const float*)d_in[2];   // [D]
    float* out = (float*)d_out;               // [T, B, D]

    dim3 ggrid(D_DIM / BN, M_DIM / BM);       // (4, 512)
    sgemm_kernel<<<ggrid, 256>>>(x, W, b);

    dim3 sgrid(BD / 256, NCH);                // (64, 8) = 512 CTAs
    scan_kernel<<<sgrid, 256>>>(out);
}

// round 5
// speedup vs baseline: 1.4654x; 1.0052x over previous
#include <cuda_runtime.h>
#include <cstdint>

// Problem dims (fixed: T=2048, B=32, D=512)
#define T_DIM 2048
#define B_DIM 32
#define D_DIM 512
#define M_DIM (T_DIM * B_DIM)   // 65536 GEMM rows
#define BD    (B_DIM * D_DIM)   // 16384 scan lanes

// Scratch: Y = x @ W^T + b (fp32, 134 MB)
__device__ float g_Y[(size_t)M_DIM * D_DIM];

// ---------------------------------------------------------------------------
// SGEMM: Y[m,e] = sum_k X[m,k]*W[e,k] + bias[e]
// CONSTRAINT: per output, fp32 fmaf chain with k strictly ascending 0..511
// (bit-matches the reference rounding; any reassociation flips spikes).
// Tile 128x256x16, 512 threads, 8x8/thread, double-buffered smem.
// ---------------------------------------------------------------------------
#define BMT 128
#define BNT 256
#define BKT 16
#define NKT (D_DIM / BKT)   // 32

__global__ __launch_bounds__(512, 1)
void sgemm_kernel(const float* __restrict__ X, const float* __restrict__ Wm,
                  const float* __restrict__ bias) {
    __shared__ __align__(16) float As[2][BKT][BMT];
    __shared__ __align__(16) float Bs[2][BKT][BNT];

    const int tid = threadIdx.x;
    const int bm  = blockIdx.y * BMT;
    const int bn  = blockIdx.x * BNT;

    // 16 warps = 4(m) x 4(n); warp tile 32m x 64n; thread tile 8x8
    const int wid    = tid >> 5;
    const int lane   = tid & 31;
    const int warp_m = wid >> 2;              // 0..3
    const int warp_n = wid & 3;               // 0..3
    const int lm     = lane >> 3;             // 0..3
    const int ln     = lane & 7;              // 0..7
    const int tm0    = warp_m * 32 + lm * 8;  // 8 consecutive m rows
    const int tn0    = warp_n * 64 + ln * 8;  // 8 consecutive n cols

    // gmem load mapping: 4 threads per row (one float4 of k each)
    const int gr = tid >> 2;                  // 0..127
    const int gk = (tid & 3) << 2;            // 0,4,8,12

    const float* Xg  = X  + (size_t)(bm + gr) * D_DIM + gk;
    const float* Wg0 = Wm + (size_t)(bn + gr) * D_DIM + gk;
    const float* Wg1 = Wm + (size_t)(bn + gr + 128) * D_DIM + gk;

    float acc[8][8];
#pragma unroll
    for (int i = 0; i < 8; i++)
#pragma unroll
        for (int j = 0; j < 8; j++) acc[i][j] = 0.0f;

    // prologue: chunk 0 -> buffer 0
    {
        float4 a  = *(const float4*)(Xg);
        float4 b0 = *(const float4*)(Wg0);
        float4 b1 = *(const float4*)(Wg1);
#pragma unroll
        for (int c = 0; c < 4; c++) {
            As[0][gk + c][gr]       = ((const float*)&a)[c];
            Bs[0][gk + c][gr]       = ((const float*)&b0)[c];
            Bs[0][gk + c][gr + 128] = ((const float*)&b1)[c];
        }
    }
    __syncthreads();

    for (int kt = 1; kt <= NKT; kt++) {
        const int buf = (kt - 1) & 1;

        float4 na, nb0, nb1;
        if (kt < NKT) {
            const int k0 = kt * BKT;
            na  = *(const float4*)(Xg + k0);
            nb0 = *(const float4*)(Wg0 + k0);
            nb1 = *(const float4*)(Wg1 + k0);
        }

#pragma unroll
        for (int k = 0; k < BKT; k++) {
            float4 a0 = *(const float4*)&As[buf][k][tm0];
            float4 a1 = *(const float4*)&As[buf][k][tm0 + 4];
            float4 b0 = *(const float4*)&Bs[buf][k][tn0];
            float4 b1 = *(const float4*)&Bs[buf][k][tn0 + 4];
            float a[8] = {a0.x, a0.y, a0.z, a0.w, a1.x, a1.y, a1.z, a1.w};
            float b[8] = {b0.x, b0.y, b0.z, b0.w, b1.x, b1.y, b1.z, b1.w};
#pragma unroll
            for (int i = 0; i < 8; i++)
#pragma unroll
                for (int j = 0; j < 8; j++)
                    acc[i][j] = fmaf(a[i], b[j], acc[i][j]);
        }

        if (kt < NKT) {
            const int nb = kt & 1;
#pragma unroll
            for (int c = 0; c < 4; c++) {
                As[nb][gk + c][gr]       = ((const float*)&na)[c];
                Bs[nb][gk + c][gr]       = ((const float*)&nb0)[c];
                Bs[nb][gk + c][gr + 128] = ((const float*)&nb1)[c];
            }
        }
        __syncthreads();
    }

    // epilogue: + bias, store Y (two STG.128 per row)
    const int colL = bn + tn0;
    const float4 biL = *(const float4*)(bias + colL);
    const float4 biH = *(const float4*)(bias + colL + 4);
#pragma unroll
    for (int i = 0; i < 8; i++) {
        const size_t row = (size_t)(bm + tm0 + i);
        float4 oL, oH;
        oL.x = acc[i][0] + biL.x; oL.y = acc[i][1] + biL.y;
        oL.z = acc[i][2] + biL.z; oL.w = acc[i][3] + biL.w;
        oH.x = acc[i][4] + biH.x; oH.y = acc[i][5] + biH.y;
        oH.z = acc[i][6] + biH.z; oH.w = acc[i][7] + biH.w;
        *(float4*)(g_Y + row * D_DIM + colL)     = oL;
        *(float4*)(g_Y + row * D_DIM + colL + 4) = oH;
    }
}

// ---------------------------------------------------------------------------
// Fused fwd+bwd LIF scan, time-chunked with warm-up (round-2, verified exact).
// ---------------------------------------------------------------------------
#define L_CH  256
#define W_UP  96
#define NCH   (T_DIM / L_CH)
#define UNR   16

__device__ __forceinline__ void lif_step(float& v, float c, bool& s) {
    v = v + (c - v) * 0.5f;
    s = (v >= 1.0f);
    v = s ? 0.0f : v;
}

__global__ void scan_kernel(float* __restrict__ out) {
    const int l  = blockIdx.x * blockDim.x + threadIdx.x;
    const int t0 = blockIdx.y * L_CH;
    unsigned fb[L_CH / 32];

    float v = 0.0f;
    {
        const int tb = (t0 - W_UP < 0) ? 0 : (t0 - W_UP);
        for (int tw = tb; tw < t0; tw += UNR) {
            float c[UNR];
#pragma unroll
            for (int i = 0; i < UNR; i++) c[i] = g_Y[(size_t)(tw + i) * BD + l];
#pragma unroll
            for (int i = 0; i < UNR; i++) { bool s; lif_step(v, c[i], s); }
        }
#pragma unroll
        for (int w = 0; w < L_CH / 32; w++) {
            unsigned bits = 0;
#pragma unroll 1
            for (int h = 0; h < 2; h++) {
                float c[UNR];
#pragma unroll
                for (int i = 0; i < UNR; i++)
                    c[i] = g_Y[(size_t)(t0 + w * 32 + h * UNR + i) * BD + l];
#pragma unroll
                for (int i = 0; i < UNR; i++) {
                    bool s; lif_step(v, c[i], s);
                    bits |= (unsigned)s << (h * UNR + i);
                }
            }
            fb[w] = bits;
        }
    }

    v = 0.0f;
    {
        const int te = (t0 + L_CH + W_UP > T_DIM) ? T_DIM : (t0 + L_CH + W_UP);
        for (int tw = te; tw > t0 + L_CH; tw -= UNR) {
            float c[UNR];
#pragma unroll
            for (int i = 0; i < UNR; i++) c[i] = g_Y[(size_t)(tw - 1 - i) * BD + l];
#pragma unroll
            for (int i = 0; i < UNR; i++) { bool s; lif_step(v, c[i], s); }
        }
#pragma unroll
        for (int w = L_CH / 32 - 1; w >= 0; w--) {
            const unsigned bits = fb[w];
#pragma unroll 1
            for (int h = 1; h >= 0; h--) {
                float c[UNR];
#pragma unroll
                for (int i = 0; i < UNR; i++)
                    c[i] = g_Y[(size_t)(t0 + w * 32 + h * UNR + (UNR - 1) - i) * BD + l];
#pragma unroll
                for (int i = 0; i < UNR; i++) {
                    const int ti = h * UNR + (UNR - 1) - i;
                    bool s; lif_step(v, c[i], s);
                    out[(size_t)(t0 + w * 32 + ti) * BD + l] =
                        (s ? 1.0f : 0.0f) + (float)((bits >> ti) & 1u);
                }
            }
        }
    }
}

// ---------------------------------------------------------------------------
extern "C" void kernel_launch(void* const* d_in, const int* in_sizes, int n_in,
                              void* d_out, int out_size) {
    const float* x = (const float*)d_in[0];
    const float* W = (const float*)d_in[1];
    const float* b = (const float*)d_in[2];
    float* out = (float*)d_out;

    dim3 ggrid(D_DIM / BNT, M_DIM / BMT);   // (2, 512) = 1024 CTAs
    sgemm_kernel<<<ggrid, 512>>>(x, W, b);

    dim3 sgrid(BD / 256, NCH);              // (64, 8)
    scan_kernel<<<sgrid, 256>>>(out);
}

// round 6
// speedup vs baseline: 1.4763x; 1.0074x over previous
#include <cuda_runtime.h>
#include <cstdint>

// Problem dims (fixed: T=2048, B=32, D=512)
#define T_DIM 2048
#define B_DIM 32
#define D_DIM 512
#define M_DIM (T_DIM * B_DIM)   // 65536 GEMM rows
#define BD    (B_DIM * D_DIM)   // 16384 scan lanes

// Scratch: Y = x @ W^T + b (fp32, 134 MB)
__device__ float g_Y[(size_t)M_DIM * D_DIM];

// ---------------------------------------------------------------------------
// SGEMM: Y[m,e] = sum_k X[m,k]*W[e,k] + bias[e]
// CONSTRAINT: per output, fp32 fmaf chain with k strictly ascending 0..511
// (bit-matches the reference rounding; any reassociation flips spikes).
// fma.rn.f32x2 pairs two adjacent n-columns: two independent IEEE fp32 FMAs
// per instruction -> same per-output rounding, half the FMA-pipe issue slots.
// ---------------------------------------------------------------------------
#define BMT 128
#define BNT 256
#define BKT 16
#define NKT (D_DIM / BKT)   // 32

typedef unsigned long long u64t;

__device__ __forceinline__ void ffma2(u64t& d, u64t a, u64t b) {
    asm("fma.rn.f32x2 %0, %1, %2, %0;" : "+l"(d) : "l"(a), "l"(b));
}
__device__ __forceinline__ u64t pack_dup(float x) {
    u64t r;
    asm("mov.b64 %0, {%1, %1};" : "=l"(r) : "f"(x));
    return r;
}
__device__ __forceinline__ void unpack2(u64t p, float& lo, float& hi) {
    asm("mov.b64 {%0, %1}, %2;" : "=f"(lo), "=f"(hi) : "l"(p));
}

__global__ __launch_bounds__(512, 1)
void sgemm_kernel(const float* __restrict__ X, const float* __restrict__ Wm,
                  const float* __restrict__ bias) {
    __shared__ __align__(16) float As[2][BKT][BMT];
    __shared__ __align__(16) float Bs[2][BKT][BNT];

    const int tid = threadIdx.x;
    const int bm  = blockIdx.y * BMT;
    const int bn  = blockIdx.x * BNT;

    // 16 warps = 4(m) x 4(n); warp tile 32m x 64n; thread tile 8m x 8n
    const int wid    = tid >> 5;
    const int lane   = tid & 31;
    const int warp_m = wid >> 2;
    const int warp_n = wid & 3;
    const int lm     = lane >> 3;
    const int ln     = lane & 7;
    const int tm0    = warp_m * 32 + lm * 8;
    const int tn0    = warp_n * 64 + ln * 8;

    // gmem load mapping: 4 threads per row (one float4 of k each)
    const int gr = tid >> 2;
    const int gk = (tid & 3) << 2;

    const float* Xg  = X  + (size_t)(bm + gr) * D_DIM + gk;
    const float* Wg0 = Wm + (size_t)(bn + gr) * D_DIM + gk;
    const float* Wg1 = Wm + (size_t)(bn + gr + 128) * D_DIM + gk;

    // acc[i][j]: rows i=0..7, n-pairs j=0..3 (cols 2j, 2j+1)
    u64t acc[8][4];
#pragma unroll
    for (int i = 0; i < 8; i++)
#pragma unroll
        for (int j = 0; j < 4; j++) acc[i][j] = 0ull;

    // prologue: chunk 0 -> buffer 0
    {
        float4 a  = *(const float4*)(Xg);
        float4 b0 = *(const float4*)(Wg0);
        float4 b1 = *(const float4*)(Wg1);
#pragma unroll
        for (int c = 0; c < 4; c++) {
            As[0][gk + c][gr]       = ((const float*)&a)[c];
            Bs[0][gk + c][gr]       = ((const float*)&b0)[c];
            Bs[0][gk + c][gr + 128] = ((const float*)&b1)[c];
        }
    }
    __syncthreads();

    for (int kt = 1; kt <= NKT; kt++) {
        const int buf = (kt - 1) & 1;

        float4 na, nb0, nb1;
        if (kt < NKT) {
            const int k0 = kt * BKT;
            na  = *(const float4*)(Xg + k0);
            nb0 = *(const float4*)(Wg0 + k0);
            nb1 = *(const float4*)(Wg1 + k0);
        }

#pragma unroll
        for (int k = 0; k < BKT; k++) {
            float4 a0 = *(const float4*)&As[buf][k][tm0];
            float4 a1 = *(const float4*)&As[buf][k][tm0 + 4];
            // B: two LDS.128, each = two natural f32x2 pairs
            ulonglong2 bp0 = *(const ulonglong2*)&Bs[buf][k][tn0];
            ulonglong2 bp1 = *(const ulonglong2*)&Bs[buf][k][tn0 + 4];
            const u64t bp[4] = {bp0.x, bp0.y, bp1.x, bp1.y};

            u64t ad[8];
            ad[0] = pack_dup(a0.x); ad[1] = pack_dup(a0.y);
            ad[2] = pack_dup(a0.z); ad[3] = pack_dup(a0.w);
            ad[4] = pack_dup(a1.x); ad[5] = pack_dup(a1.y);
            ad[6] = pack_dup(a1.z); ad[7] = pack_dup(a1.w);

#pragma unroll
            for (int i = 0; i < 8; i++)
#pragma unroll
                for (int j = 0; j < 4; j++)
                    ffma2(acc[i][j], ad[i], bp[j]);
        }

        if (kt < NKT) {
            const int nb = kt & 1;
#pragma unroll
            for (int c = 0; c < 4; c++) {
                As[nb][gk + c][gr]       = ((const float*)&na)[c];
                Bs[nb][gk + c][gr]       = ((const float*)&nb0)[c];
                Bs[nb][gk + c][gr + 128] = ((const float*)&nb1)[c];
            }
        }
        __syncthreads();
    }

    // epilogue: + bias (scalar fp32 adds, bit-identical), store Y
    const int colL = bn + tn0;
    const float4 biL = *(const float4*)(bias + colL);
    const float4 biH = *(const float4*)(bias + colL + 4);
#pragma unroll
    for (int i = 0; i < 8; i++) {
        const size_t row = (size_t)(bm + tm0 + i);
        float v0, v1, v2, v3, v4, v5, v6, v7;
        unpack2(acc[i][0], v0, v1);
        unpack2(acc[i][1], v2, v3);
        unpack2(acc[i][2], v4, v5);
        unpack2(acc[i][3], v6, v7);
        float4 oL = {v0 + biL.x, v1 + biL.y, v2 + biL.z, v3 + biL.w};
        float4 oH = {v4 + biH.x, v5 + biH.y, v6 + biH.z, v7 + biH.w};
        *(float4*)(g_Y + row * D_DIM + colL)     = oL;
        *(float4*)(g_Y + row * D_DIM + colL + 4) = oH;
    }
}

// ---------------------------------------------------------------------------
// Fused fwd+bwd LIF scan, time-chunked with warm-up (verified exact).
// ---------------------------------------------------------------------------
#define L_CH  256
#define W_UP  96
#define NCH   (T_DIM / L_CH)
#define UNR   16

__device__ __forceinline__ void lif_step(float& v, float c, bool& s) {
    v = v + (c - v) * 0.5f;
    s = (v >= 1.0f);
    v = s ? 0.0f : v;
}

__global__ void scan_kernel(float* __restrict__ out) {
    const int l  = blockIdx.x * blockDim.x + threadIdx.x;
    const int t0 = blockIdx.y * L_CH;
    unsigned fb[L_CH / 32];

    float v = 0.0f;
    {
        const int tb = (t0 - W_UP < 0) ? 0 : (t0 - W_UP);
        for (int tw = tb; tw < t0; tw += UNR) {
            float c[UNR];
#pragma unroll
            for (int i = 0; i < UNR; i++) c[i] = g_Y[(size_t)(tw + i) * BD + l];
#pragma unroll
            for (int i = 0; i < UNR; i++) { bool s; lif_step(v, c[i], s); }
        }
#pragma unroll
        for (int w = 0; w < L_CH / 32; w++) {
            unsigned bits = 0;
#pragma unroll 1
            for (int h = 0; h < 2; h++) {
                float c[UNR];
#pragma unroll
                for (int i = 0; i < UNR; i++)
                    c[i] = g_Y[(size_t)(t0 + w * 32 + h * UNR + i) * BD + l];
#pragma unroll
                for (int i = 0; i < UNR; i++) {
                    bool s; lif_step(v, c[i], s);
                    bits |= (unsigned)s << (h * UNR + i);
                }
            }
            fb[w] = bits;
        }
    }

    v = 0.0f;
    {
        const int te = (t0 + L_CH + W_UP > T_DIM) ? T_DIM : (t0 + L_CH + W_UP);
        for (int tw = te; tw > t0 + L_CH; tw -= UNR) {
            float c[UNR];
#pragma unroll
            for (int i = 0; i < UNR; i++) c[i] = g_Y[(size_t)(tw - 1 - i) * BD + l];
#pragma unroll
            for (int i = 0; i < UNR; i++) { bool s; lif_step(v, c[i], s); }
        }
#pragma unroll
        for (int w = L_CH / 32 - 1; w >= 0; w--) {
            const unsigned bits = fb[w];
#pragma unroll 1
            for (int h = 1; h >= 0; h--) {
                float c[UNR];
#pragma unroll
                for (int i = 0; i < UNR; i++)
                    c[i] = g_Y[(size_t)(t0 + w * 32 + h * UNR + (UNR - 1) - i) * BD + l];
#pragma unroll
                for (int i = 0; i < UNR; i++) {
                    const int ti = h * UNR + (UNR - 1) - i;
                    bool s; lif_step(v, c[i], s);
                    out[(size_t)(t0 + w * 32 + ti) * BD + l] =
                        (s ? 1.0f : 0.0f) + (float)((bits >> ti) & 1u);
                }
            }
        }
    }
}

// ---------------------------------------------------------------------------
extern "C" void kernel_launch(void* const* d_in, const int* in_sizes, int n_in,
                              void* d_out, int out_size) {
    const float* x = (const float*)d_in[0];
    const float* W = (const float*)d_in[1];
    const float* b = (const float*)d_in[2];
    float* out = (float*)d_out;

    dim3 ggrid(D_DIM / BNT, M_DIM / BMT);   // (2, 512) = 1024 CTAs
    sgemm_kernel<<<ggrid, 512>>>(x, W, b);

    dim3 sgrid(BD / 256, NCH);              // (64, 8)
    scan_kernel<<<sgrid, 256>>>(out);
}

// round 8
// speedup vs baseline: 1.7366x; 1.1763x over previous
#include <cuda_runtime.h>
#include <cstdint>

// Problem dims (fixed: T=2048, B=32, D=512)
#define T_DIM 2048
#define B_DIM 32
#define D_DIM 512
#define M_DIM (T_DIM * B_DIM)   // 65536 GEMM rows
#define BD    (B_DIM * D_DIM)   // 16384 scan lanes

// Scratch: Y = x @ W^T + b (fp32, 134 MB)
__device__ float g_Y[(size_t)M_DIM * D_DIM];

// ---------------------------------------------------------------------------
// SGEMM: Y[m,e] = sum_k X[m,k]*W[e,k] + bias[e]
// CONSTRAINT: per output, fp32 fmaf chain with k strictly ascending 0..511
// (bit-matches the reference rounding; any reassociation flips spikes).
// Thread tile 8m x 16n (FLOP/smem-byte up 1.8x vs 8x8 -> crossbar unbound),
// fma.rn.f32x2 for paired n-columns (independent IEEE fp32 lanes, bit-exact).
// CTA 128m x 256n x k16, 256 threads, 8 warps (4m x 2n), double-buffered.
// Grid (M/128, D/256): bn = blockIdx.y*256 (round-7 bug: this was missing).
// ---------------------------------------------------------------------------
#define BMT 128
#define BNT 256
#define BKT 16
#define NKT (D_DIM / BKT)   // 32

typedef unsigned long long u64t;

__device__ __forceinline__ void ffma2(u64t& d, u64t a, u64t b) {
    asm("fma.rn.f32x2 %0, %1, %2, %0;" : "+l"(d) : "l"(a), "l"(b));
}
__device__ __forceinline__ u64t pack_dup(float x) {
    u64t r;
    asm("mov.b64 %0, {%1, %1};" : "=l"(r) : "f"(x));
    return r;
}
__device__ __forceinline__ void unpack2(u64t p, float& lo, float& hi) {
    asm("mov.b64 {%0, %1}, %2;" : "=f"(lo), "=f"(hi) : "l"(p));
}

__global__ __launch_bounds__(256, 1)
void sgemm_kernel(const float* __restrict__ X, const float* __restrict__ Wm,
                  const float* __restrict__ bias) {
    __shared__ __align__(16) float As[2][BKT][BMT];   // 16 KB
    __shared__ __align__(16) float Bs[2][BKT][BNT];   // 32 KB

    const int tid = threadIdx.x;
    const int bm  = blockIdx.x * BMT;
    const int bn  = blockIdx.y * BNT;

    // 8 warps = 4(m) x 2(n); warp tile 32m x 128n; thread tile 8m x 16n
    const int wid    = tid >> 5;
    const int lane   = tid & 31;
    const int warp_m = wid >> 1;              // 0..3
    const int warp_n = wid & 1;               // 0..1
    const int lm     = lane >> 3;             // 0..3
    const int ln     = lane & 7;              // 0..7
    const int tm0    = warp_m * 32 + lm * 8;  // 8 consecutive m rows
    const int bn0    = warp_n * 128 + ln * 4; // + q*32, q=0..3 (4 cols each)

    // gmem load mapping: 4 threads per row (one float4 of k each)
    const int gr = tid >> 2;                  // 0..63
    const int gk = (tid & 3) << 2;            // 0,4,8,12

    const float* Xg = X  + (size_t)(bm + gr) * D_DIM + gk;
    const float* Wg = Wm + (size_t)(bn + gr) * D_DIM + gk;

    // acc[i][j]: rows i=0..7, n-pair j -> cols bn+bn0 + (j>>1)*32 + (j&1)*2 ..+1
    u64t acc[8][8];
#pragma unroll
    for (int i = 0; i < 8; i++)
#pragma unroll
        for (int j = 0; j < 8; j++) acc[i][j] = 0ull;

    // prologue: chunk 0 -> buffer 0
    {
        float4 a0 = *(const float4*)(Xg);
        float4 a1 = *(const float4*)(Xg + (size_t)64 * D_DIM);
#pragma unroll
        for (int c = 0; c < 4; c++) {
            As[0][gk + c][gr]      = ((const float*)&a0)[c];
            As[0][gk + c][gr + 64] = ((const float*)&a1)[c];
        }
#pragma unroll
        for (int s = 0; s < 4; s++) {
            float4 b = *(const float4*)(Wg + (size_t)(s * 64) * D_DIM);
#pragma unroll
            for (int c = 0; c < 4; c++)
                Bs[0][gk + c][gr + s * 64] = ((const float*)&b)[c];
        }
    }
    __syncthreads();

    for (int kt = 1; kt <= NKT; kt++) {
        const int buf = (kt - 1) & 1;

        float4 na0, na1, nb[4];
        if (kt < NKT) {
            const int k0 = kt * BKT;
            na0 = *(const float4*)(Xg + k0);
            na1 = *(const float4*)(Xg + k0 + (size_t)64 * D_DIM);
#pragma unroll
            for (int s = 0; s < 4; s++)
                nb[s] = *(const float4*)(Wg + k0 + (size_t)(s * 64) * D_DIM);
        }

#pragma unroll
        for (int k = 0; k < BKT; k++) {
            float4 a0 = *(const float4*)&As[buf][k][tm0];
            float4 a1 = *(const float4*)&As[buf][k][tm0 + 4];
            u64t ad[8];
            ad[0] = pack_dup(a0.x); ad[1] = pack_dup(a0.y);
            ad[2] = pack_dup(a0.z); ad[3] = pack_dup(a0.w);
            ad[4] = pack_dup(a1.x); ad[5] = pack_dup(a1.y);
            ad[6] = pack_dup(a1.z); ad[7] = pack_dup(a1.w);

            u64t bp[8];
#pragma unroll
            for (int q = 0; q < 4; q++) {
                // 8 lanes (ln) cover one contiguous 128B block: conflict-free
                ulonglong2 b2 = *(const ulonglong2*)&Bs[buf][k][bn0 + q * 32];
                bp[q * 2 + 0] = b2.x;
                bp[q * 2 + 1] = b2.y;
            }

#pragma unroll
            for (int i = 0; i < 8; i++)
#pragma unroll
                for (int j = 0; j < 8; j++)
                    ffma2(acc[i][j], ad[i], bp[j]);
        }

        if (kt < NKT) {
            const int nbuf = kt & 1;
#pragma unroll
            for (int c = 0; c < 4; c++) {
                As[nbuf][gk + c][gr]      = ((const float*)&na0)[c];
                As[nbuf][gk + c][gr + 64] = ((const float*)&na1)[c];
            }
#pragma unroll
            for (int s = 0; s < 4; s++)
#pragma unroll
                for (int c = 0; c < 4; c++)
                    Bs[nbuf][gk + c][gr + s * 64] = ((const float*)&nb[s])[c];
        }
        __syncthreads();
    }

    // epilogue: + bias (scalar fp32 adds, bit-identical), store Y
#pragma unroll
    for (int q = 0; q < 4; q++) {
        const int col = bn + bn0 + q * 32;
        const float4 bi = *(const float4*)(bias + col);
#pragma unroll
        for (int i = 0; i < 8; i++) {
            float v0, v1, v2, v3;
            unpack2(acc[i][q * 2 + 0], v0, v1);
            unpack2(acc[i][q * 2 + 1], v2, v3);
            float4 o = {v0 + bi.x, v1 + bi.y, v2 + bi.z, v3 + bi.w};
            *(float4*)(g_Y + (size_t)(bm + tm0 + i) * D_DIM + col) = o;
        }
    }
}

// ---------------------------------------------------------------------------
// Fused fwd+bwd LIF scan, time-chunked with warm-up (verified exact).
// ---------------------------------------------------------------------------
#define L_CH  256
#define W_UP  96
#define NCH   (T_DIM / L_CH)
#define UNR   16

__device__ __forceinline__ void lif_step(float& v, float c, bool& s) {
    v = v + (c - v) * 0.5f;
    s = (v >= 1.0f);
    v = s ? 0.0f : v;
}

__global__ void scan_kernel(float* __restrict__ out) {
    const int l  = blockIdx.x * blockDim.x + threadIdx.x;
    const int t0 = blockIdx.y * L_CH;
    unsigned fb[L_CH / 32];

    float v = 0.0f;
    {
        const int tb = (t0 - W_UP < 0) ? 0 : (t0 - W_UP);
        for (int tw = tb; tw < t0; tw += UNR) {
            float c[UNR];
#pragma unroll
            for (int i = 0; i < UNR; i++) c[i] = g_Y[(size_t)(tw + i) * BD + l];
#pragma unroll
            for (int i = 0; i < UNR; i++) { bool s; lif_step(v, c[i], s); }
        }
#pragma unroll
        for (int w = 0; w < L_CH / 32; w++) {
            unsigned bits = 0;
#pragma unroll 1
            for (int h = 0; h < 2; h++) {
                float c[UNR];
#pragma unroll
                for (int i = 0; i < UNR; i++)
                    c[i] = g_Y[(size_t)(t0 + w * 32 + h * UNR + i) * BD + l];
#pragma unroll
                for (int i = 0; i < UNR; i++) {
                    bool s; lif_step(v, c[i], s);
                    bits |= (unsigned)s << (h * UNR + i);
                }
            }
            fb[w] = bits;
        }
    }

    v = 0.0f;
    {
        const int te = (t0 + L_CH + W_UP > T_DIM) ? T_DIM : (t0 + L_CH + W_UP);
        for (int tw = te; tw > t0 + L_CH; tw -= UNR) {
            float c[UNR];
#pragma unroll
            for (int i = 0; i < UNR; i++) c[i] = g_Y[(size_t)(tw - 1 - i) * BD + l];
#pragma unroll
            for (int i = 0; i < UNR; i++) { bool s; lif_step(v, c[i], s); }
        }
#pragma unroll
        for (int w = L_CH / 32 - 1; w >= 0; w--) {
            const unsigned bits = fb[w];
#pragma unroll 1
            for (int h = 1; h >= 0; h--) {
                float c[UNR];
#pragma unroll
                for (int i = 0; i < UNR; i++)
                    c[i] = g_Y[(size_t)(t0 + w * 32 + h * UNR + (UNR - 1) - i) * BD + l];
#pragma unroll
                for (int i = 0; i < UNR; i++) {
                    const int ti = h * UNR + (UNR - 1) - i;
                    bool s; lif_step(v, c[i], s);
                    out[(size_t)(t0 + w * 32 + ti) * BD + l] =
                        (s ? 1.0f : 0.0f) + (float)((bits >> ti) & 1u);
                }
            }
        }
    }
}

// ---------------------------------------------------------------------------
extern "C" void kernel_launch(void* const* d_in, const int* in_sizes, int n_in,
                              void* d_out, int out_size) {
    const float* x = (const float*)d_in[0];
    const float* W = (const float*)d_in[1];
    const float* b = (const float*)d_in[2];
    float* out = (float*)d_out;

    dim3 ggrid(M_DIM / BMT, D_DIM / BNT);   // (512, 2) = 1024 CTAs
    sgemm_kernel<<<ggrid, 256>>>(x, W, b);

    dim3 sgrid(BD / 256, NCH);              // (64, 8)
    scan_kernel<<<sgrid, 256>>>(out);
}